// round 12
// baseline (speedup 1.0000x reference)
#include <cuda_runtime.h>
#include <cuda_fp16.h>
#include <stdint.h>

// Problem dims (fixed): B=4, S=2048, D=1024, H=16, HD=64
#define LOG2E 1.4426950408889634f
#define SCL   (0.125f * 1.4426950408889634f)   // 1/sqrt(64) * log2(e)

// ---------------- device scratch (static: allocation-free at launch) -------
__device__ __half g_Xh[8192 * 1024];          // hidden in fp16        (16 MB)
__device__ __half g_Wh[3][1024 * 1024];       // Wq/Wk/Wv in fp16      ( 6 MB)
__device__ __half g_Q [64 * 2048 * 64];       // Q  [bh][s][hd]        (16 MB)
__device__ __half g_K [64 * 2048 * 64];       // K  [bh][s][hd]        (16 MB)
__device__ __half g_Vt[64 * 64 * 2048];       // V^T [bh][hd][s]       (16 MB)

// ---------------- helpers ----------------------------------------------------
__device__ __forceinline__ uint32_t smem_u32(const void* p) {
    return (uint32_t)__cvta_generic_to_shared(p);
}
__device__ __forceinline__ void ldm4(uint32_t* r, uint32_t a) {
    asm volatile("ldmatrix.sync.aligned.m8n8.x4.shared.b16 {%0,%1,%2,%3}, [%4];"
                 : "=r"(r[0]), "=r"(r[1]), "=r"(r[2]), "=r"(r[3]) : "r"(a));
}
__device__ __forceinline__ void mma16816(float* c, const uint32_t* a, const uint32_t* b) {
    asm volatile(
        "mma.sync.aligned.m16n8k16.row.col.f32.f16.f16.f32 "
        "{%0,%1,%2,%3}, {%4,%5,%6,%7}, {%8,%9}, {%0,%1,%2,%3};"
        : "+f"(c[0]), "+f"(c[1]), "+f"(c[2]), "+f"(c[3])
        : "r"(a[0]), "r"(a[1]), "r"(a[2]), "r"(a[3]), "r"(b[0]), "r"(b[1]));
}
__device__ __forceinline__ void cpa16(uint32_t dst, const void* src) {
    asm volatile("cp.async.cg.shared.global [%0], [%1], 16;" :: "r"(dst), "l"(src));
}
#define CP_COMMIT() asm volatile("cp.async.commit_group;")
#define CP_WAIT(n)  asm volatile("cp.async.wait_group %0;" :: "n"(n))

__device__ __forceinline__ uint32_t h2ex2(float a, float b, __half2 clamp) {
    __half2 h = __hmin2(__floats2half2_rn(a, b), clamp);
    uint32_t r, x = *reinterpret_cast<uint32_t*>(&h);
    asm volatile("ex2.approx.f16x2 %0, %1;" : "=r"(r) : "r"(x));
    return r;
}

// ---------------- fp32 -> fp16 convert (X + all 3 W in one launch) ----------
__global__ void cvt_all(const float4* __restrict__ x,
                        const float4* __restrict__ wq,
                        const float4* __restrict__ wk,
                        const float4* __restrict__ wv) {
    int bid = blockIdx.x;
    const float4* src;
    __half2* dst;
    int i;
    if (bid < 8192) {                       // X: 2097152 float4s
        src = x; dst = (__half2*)g_Xh;
        i = bid * 256 + threadIdx.x;
    } else {                                // W[z]: 262144 float4s each
        int r = bid - 8192;
        int z = r >> 10;
        src = (z == 0) ? wq : (z == 1) ? wk : wv;
        dst = (__half2*)g_Wh[z];
        i = (r & 1023) * 256 + threadIdx.x;
    }
    float4 v = src[i];
    dst[2 * i + 0] = __floats2half2_rn(v.x, v.y);
    dst[2 * i + 1] = __floats2half2_rn(v.z, v.w);
}

// ---------------- fused QKV projection (3-stage pipeline, unchanged) --------
// BK=64, CTA tile 128x128, 8 warps (warp tile 64x32), occupancy 2.
// smem: A stages [3][128][72]h at 0 (55296 B), B stages at 55296. 110592 B.
#define QKV_SMEM 110592
__global__ __launch_bounds__(256, 2) void qkv_gemm(const float* __restrict__ bq,
                                                   const float* __restrict__ bk,
                                                   const float* __restrict__ bv) {
    extern __shared__ char qsm[];

    const int z  = blockIdx.z;
    const __half* W    = g_Wh[z];
    const float*  bias = (z == 0) ? bq : (z == 1) ? bk : bv;
    const int m0 = blockIdx.y * 128;
    const int n0 = blockIdx.x * 128;

    const int t    = threadIdx.x;
    const int warp = t >> 5, lane = t & 31;
    const int wm = warp & 1, wn = warp >> 1;

    auto load_st = [&](int st, int kb) {
#pragma unroll
        for (int i = 0; i < 4; i++) {
            int idx = t + i * 256;              // 1024 chunks of 16B per tile
            int row = idx >> 3, c = idx & 7;
            cpa16(smem_u32(qsm + st * 18432 + row * 144 + c * 16),
                  g_Xh + (size_t)(m0 + row) * 1024 + kb * 64 + c * 8);
            cpa16(smem_u32(qsm + 55296 + st * 18432 + row * 144 + c * 16),
                  W + (size_t)(n0 + row) * 1024 + kb * 64 + c * 8);
        }
    };

    float acc[4][4][4];
#pragma unroll
    for (int i = 0; i < 4; i++)
#pragma unroll
        for (int j = 0; j < 4; j++)
#pragma unroll
            for (int k = 0; k < 4; k++) acc[i][j][k] = 0.f;

    const uint32_t aOff = (uint32_t)(wm * 64 + (lane & 15)) * 144 + (lane >> 4) * 16;
    const uint32_t bOff = (uint32_t)(wn * 32 + (lane & 7) + ((lane >> 4) & 1) * 8) * 144
                        + ((lane >> 3) & 1) * 16;

    load_st(0, 0);
    CP_COMMIT();
    load_st(1, 1);
    CP_COMMIT();

    int st = 0;
    for (int kb = 0; kb < 16; kb++) {
        CP_WAIT(1);
        __syncthreads();
        if (kb + 2 < 16) load_st((kb + 2) % 3, kb + 2);
        CP_COMMIT();

        const uint32_t aAddr = smem_u32(qsm) + st * 18432 + aOff;
        const uint32_t bAddr = smem_u32(qsm) + 55296 + st * 18432 + bOff;
        st = (st == 2) ? 0 : st + 1;
#pragma unroll
        for (int kc = 0; kc < 4; kc++) {
            uint32_t a[4][4], b[2][4];
#pragma unroll
            for (int mt = 0; mt < 4; mt++) ldm4(a[mt], aAddr + kc * 32 + mt * 16 * 144);
#pragma unroll
            for (int np = 0; np < 2; np++) ldm4(b[np], bAddr + kc * 32 + np * 16 * 144);
#pragma unroll
            for (int mt = 0; mt < 4; mt++)
#pragma unroll
                for (int nt = 0; nt < 4; nt++)
                    mma16816(acc[mt][nt], a[mt], b[nt >> 1] + (nt & 1) * 2);
        }
    }

    // epilogue: bias + store into head-major scratch (fp16)
#pragma unroll
    for (int mt = 0; mt < 4; mt++) {
        int m  = m0 + wm * 64 + mt * 16 + (lane >> 2);
        int bb = m >> 11;
        int s  = m & 2047;
#pragma unroll
        for (int nt = 0; nt < 4; nt++) {
            int n  = n0 + wn * 32 + nt * 8 + (lane & 3) * 2;
            int h  = n >> 6, hd = n & 63;
            int bh = bb * 16 + h;
            float bs0 = bias[n], bs1 = bias[n + 1];
            float v00 = acc[mt][nt][0] + bs0, v01 = acc[mt][nt][1] + bs1;
            float v10 = acc[mt][nt][2] + bs0, v11 = acc[mt][nt][3] + bs1;
            if (z < 2) {
                __half* dst = (z == 0) ? g_Q : g_K;
                *(__half2*)&dst[((size_t)bh * 2048 + s    ) * 64 + hd] = __floats2half2_rn(v00, v01);
                *(__half2*)&dst[((size_t)bh * 2048 + s + 8) * 64 + hd] = __floats2half2_rn(v10, v11);
            } else {
                g_Vt[((size_t)bh * 64 + hd    ) * 2048 + s    ] = __float2half_rn(v00);
                g_Vt[((size_t)bh * 64 + hd + 1) * 2048 + s    ] = __float2half_rn(v01);
                g_Vt[((size_t)bh * 64 + hd    ) * 2048 + s + 8] = __float2half_rn(v10);
                g_Vt[((size_t)bh * 64 + hd + 1) * 2048 + s + 8] = __float2half_rn(v11);
            }
        }
    }
}

// ---------------- FlashAttention (chunk-fused, occupancy 3) -----------------
// 128 q-rows / CTA, 4 warps x (2 m-tiles of 16 rows). Per 16-key chunk np:
// score MMA -> softmax -> PV MMA immediately, so the transient score block is
// only 16 regs (was 64) and the kernel fits 3 CTAs/SM (12 warps -> 3/SMSP,
// cross-warp phase skew overlaps MUFU/FMA with HMMA).
// smem layout (bytes):
//   Qs [128][72] half : 0      .. 18432
//   Ks [3][64][72]    : 18432  .. 46080   (stage = 9216)
//   Vs [3][64][72]    : 46080  .. 73728
//   mk [3][64] float  : 73728  .. 74496
#define ATTN_SMEM 74496
__global__ __launch_bounds__(128, 3) void attn_kernel(const float* __restrict__ mask,
                                                      float* __restrict__ out) {
    extern __shared__ char sm[];
    __half (*Qs)[72] = (__half(*)[72])sm;
    char* ksBase = sm + 18432;
    char* vsBase = sm + 46080;
    float* mkBase = (float*)(sm + 73728);

    const int bh = blockIdx.y;
    const int q0 = blockIdx.x * 128;
    const int b  = bh >> 4, h = bh & 15;
    const int t = threadIdx.x, warp = t >> 5, lane = t & 31;
    const __half2 clamp14 = __floats2half2_rn(14.f, 14.f);

    auto load_kv = [&](int st, int k0) {
#pragma unroll
        for (int i = 0; i < 4; i++) {
            int idx = t + i * 128;           // 512 chunks of 16B per tile
            int row = idx >> 3, cb = idx & 7;
            cpa16(smem_u32(ksBase + st * 9216 + row * 144 + cb * 16),
                  &g_K[((size_t)bh * 2048 + k0 + row) * 64 + cb * 8]);
            cpa16(smem_u32(vsBase + st * 9216 + row * 144 + cb * 16),
                  &g_Vt[((size_t)bh * 64 + row) * 2048 + k0 + cb * 8]);
        }
        if (t < 64)
            mkBase[st * 64 + t] = mask[b * 2048 + k0 + t] * LOG2E;
    };

    load_kv(0, 0);
    CP_COMMIT();
    load_kv(1, 64);
    CP_COMMIT();

#pragma unroll
    for (int i = 0; i < 8; i++) {
        int idx = t + i * 128;              // 1024 chunks for the 128x64 Q tile
        int row = idx >> 3, c8 = (idx & 7) * 8;
        *(uint4*)&Qs[row][c8] =
            *(const uint4*)&g_Q[((size_t)bh * 2048 + q0 + row) * 64 + c8];
    }
    __syncthreads();

    // Q fragments: 2 m-tiles x 4 k-chunks
    uint32_t qa[2][4][4];
#pragma unroll
    for (int mt = 0; mt < 2; mt++) {
        uint32_t qAddr = smem_u32(&Qs[warp * 32 + mt * 16 + (lane & 15)][(lane >> 4) * 8]);
#pragma unroll
        for (int ks = 0; ks < 4; ks++) ldm4(qa[mt][ks], qAddr + ks * 32);
    }

    const uint32_t kOff = ((lane & 7) + ((lane >> 4) & 1) * 8) * 144 + ((lane >> 3) & 1) * 16;
    const uint32_t kA0 = smem_u32(ksBase) + kOff;
    const uint32_t vA0 = smem_u32(vsBase) + kOff;

    float o[2][8][4];
#pragma unroll
    for (int mt = 0; mt < 2; mt++)
#pragma unroll
        for (int i = 0; i < 8; i++)
#pragma unroll
            for (int j = 0; j < 4; j++) o[mt][i][j] = 0.f;
    float l00 = 0.f, l01 = 0.f, l10 = 0.f, l11 = 0.f;

    int st = 0;
    for (int kt = 0; kt < 32; kt++) {
        CP_WAIT(1);                    // stage kt resident; kt+1 may be in flight
        __syncthreads();               // stage (kt+2)%3 fully consumed
        if (kt + 2 < 32) load_kv((kt + 2) % 3, (kt + 2) * 64);
        CP_COMMIT();

        const uint32_t kA = kA0 + st * 9216;
        const uint32_t vA = vA0 + st * 9216;
        const float* mk = mkBase + st * 64;
        st = (st == 2) ? 0 : st + 1;

        // per 16-key chunk: scores -> softmax -> PV (short dependency chain,
        // transient score block = 16 regs)
#pragma unroll
        for (int np = 0; np < 4; np++) {
            float s2[2][2][4];
#pragma unroll
            for (int mt = 0; mt < 2; mt++)
#pragma unroll
                for (int u = 0; u < 2; u++)
#pragma unroll
                    for (int j = 0; j < 4; j++) s2[mt][u][j] = 0.f;
#pragma unroll
            for (int ks = 0; ks < 4; ks++) {
                uint32_t kf[4];
                ldm4(kf, kA + np * 16 * 144 + ks * 32);
#pragma unroll
                for (int mt = 0; mt < 2; mt++) {
                    mma16816(s2[mt][0], qa[mt][ks], kf);
                    mma16816(s2[mt][1], qa[mt][ks], kf + 2);
                }
            }

            uint32_t ph[2][4];
#pragma unroll
            for (int mt = 0; mt < 2; mt++) {
                float lp0 = 0.f, lp1 = 0.f;
#pragma unroll
                for (int u = 0; u < 2; u++) {
                    int key = (2 * np + u) * 8 + (lane & 3) * 2;
                    float mk0v = mk[key], mk1v = mk[key + 1];
                    float a0 = fmaf(s2[mt][u][0], SCL, mk0v);
                    float a1 = fmaf(s2[mt][u][1], SCL, mk1v);
                    float a2 = fmaf(s2[mt][u][2], SCL, mk0v);
                    float a3 = fmaf(s2[mt][u][3], SCL, mk1v);
                    ph[mt][2*u    ] = h2ex2(a0, a1, clamp14);
                    ph[mt][2*u + 1] = h2ex2(a2, a3, clamp14);
                    float2 f0 = __half22float2(*reinterpret_cast<__half2*>(&ph[mt][2*u]));
                    float2 f1 = __half22float2(*reinterpret_cast<__half2*>(&ph[mt][2*u+1]));
                    lp0 += f0.x + f0.y;
                    lp1 += f1.x + f1.y;
                }
                if (mt == 0) { l00 += lp0; l01 += lp1; }
                else         { l10 += lp0; l11 += lp1; }
            }

#pragma unroll
            for (int hp = 0; hp < 4; hp++) {
                uint32_t vf[4];
                ldm4(vf, vA + hp * 16 * 144 + np * 32);
#pragma unroll
                for (int mt = 0; mt < 2; mt++) {
                    mma16816(o[mt][2*hp    ], ph[mt], vf);
                    mma16816(o[mt][2*hp + 1], ph[mt], vf + 2);
                }
            }
        }
    }

    // epilogue: one cross-lane reduction, normalize, store fp32 [B,S,D]
    l00 += __shfl_xor_sync(0xffffffffu, l00, 1);
    l00 += __shfl_xor_sync(0xffffffffu, l00, 2);
    l01 += __shfl_xor_sync(0xffffffffu, l01, 1);
    l01 += __shfl_xor_sync(0xffffffffu, l01, 2);
    l10 += __shfl_xor_sync(0xffffffffu, l10, 1);
    l10 += __shfl_xor_sync(0xffffffffu, l10, 2);
    l11 += __shfl_xor_sync(0xffffffffu, l11, 1);
    l11 += __shfl_xor_sync(0xffffffffu, l11, 2);
    const int cb = h * 64 + (lane & 3) * 2;
#pragma unroll
    for (int mt = 0; mt < 2; mt++) {
        float rl0 = 1.f / (mt ? l10 : l00);
        float rl1 = 1.f / (mt ? l11 : l01);
        int s0 = q0 + warp * 32 + mt * 16 + (lane >> 2);
#pragma unroll
        for (int ht = 0; ht < 8; ht++) {
            int c = cb + ht * 8;
            float2 v0 = make_float2(o[mt][ht][0] * rl0, o[mt][ht][1] * rl0);
            float2 v1 = make_float2(o[mt][ht][2] * rl1, o[mt][ht][3] * rl1);
            *(float2*)&out[((size_t)b * 2048 + s0    ) * 1024 + c] = v0;
            *(float2*)&out[((size_t)b * 2048 + s0 + 8) * 1024 + c] = v1;
        }
    }
}

// ---------------- launch -----------------------------------------------------
extern "C" void kernel_launch(void* const* d_in, const int* in_sizes, int n_in,
                              void* d_out, int out_size) {
    const float* hidden = (const float*)d_in[0];
    const float* mask   = (const float*)d_in[1];
    const float* Wq     = (const float*)d_in[2];
    const float* bq     = (const float*)d_in[3];
    const float* Wk     = (const float*)d_in[4];
    const float* bk     = (const float*)d_in[5];
    const float* Wv     = (const float*)d_in[6];
    const float* bv     = (const float*)d_in[7];
    float* out = (float*)d_out;

    cudaFuncSetAttribute(qkv_gemm, cudaFuncAttributeMaxDynamicSharedMemorySize, QKV_SMEM);
    cudaFuncSetAttribute(attn_kernel, cudaFuncAttributeMaxDynamicSharedMemorySize, ATTN_SMEM);

    cvt_all<<<11264, 256>>>((const float4*)hidden, (const float4*)Wq,
                            (const float4*)Wk, (const float4*)Wv);

    dim3 g1(8, 64, 3);      // N-blocks, M-blocks, {Q,K,V}
    qkv_gemm<<<g1, 256, QKV_SMEM>>>(bq, bk, bv);

    dim3 g2(16, 64);        // q-tiles (128 rows), B*H
    attn_kernel<<<g2, 128, ATTN_SMEM>>>(mask, out);
}

// round 13
// speedup vs baseline: 1.0050x; 1.0050x over previous
#include <cuda_runtime.h>
#include <cuda_fp16.h>
#include <stdint.h>

// Problem dims (fixed): B=4, S=2048, D=1024, H=16, HD=64
#define LOG2E 1.4426950408889634f
#define SCL   (0.125f * 1.4426950408889634f)   // 1/sqrt(64) * log2(e)

// ---------------- device scratch (static: allocation-free at launch) -------
__device__ __half g_Xh[8192 * 1024];          // hidden in fp16        (16 MB)
__device__ __half g_Wh[3][1024 * 1024];       // Wq/Wk/Wv in fp16      ( 6 MB)
__device__ __half g_Q [64 * 2048 * 64];       // Q  [bh][s][hd]        (16 MB)
__device__ __half g_K [64 * 2048 * 64];       // K  [bh][s][hd]        (16 MB)
__device__ __half g_Vt[64 * 64 * 2048];       // V^T [bh][hd][s]       (16 MB)

// ---------------- helpers ----------------------------------------------------
__device__ __forceinline__ uint32_t smem_u32(const void* p) {
    return (uint32_t)__cvta_generic_to_shared(p);
}
__device__ __forceinline__ void ldm4(uint32_t* r, uint32_t a) {
    asm volatile("ldmatrix.sync.aligned.m8n8.x4.shared.b16 {%0,%1,%2,%3}, [%4];"
                 : "=r"(r[0]), "=r"(r[1]), "=r"(r[2]), "=r"(r[3]) : "r"(a));
}
__device__ __forceinline__ void mma16816(float* c, const uint32_t* a, const uint32_t* b) {
    asm volatile(
        "mma.sync.aligned.m16n8k16.row.col.f32.f16.f16.f32 "
        "{%0,%1,%2,%3}, {%4,%5,%6,%7}, {%8,%9}, {%0,%1,%2,%3};"
        : "+f"(c[0]), "+f"(c[1]), "+f"(c[2]), "+f"(c[3])
        : "r"(a[0]), "r"(a[1]), "r"(a[2]), "r"(a[3]), "r"(b[0]), "r"(b[1]));
}
__device__ __forceinline__ void cpa16(uint32_t dst, const void* src) {
    asm volatile("cp.async.cg.shared.global [%0], [%1], 16;" :: "r"(dst), "l"(src));
}
#define CP_COMMIT() asm volatile("cp.async.commit_group;")
#define CP_WAIT(n)  asm volatile("cp.async.wait_group %0;" :: "n"(n))

__device__ __forceinline__ uint32_t h2ex2(float a, float b, __half2 clamp) {
    __half2 h = __hmin2(__floats2half2_rn(a, b), clamp);
    uint32_t r, x = *reinterpret_cast<uint32_t*>(&h);
    asm volatile("ex2.approx.f16x2 %0, %1;" : "=r"(r) : "r"(x));
    return r;
}

// ---------------- fp32 -> fp16 convert (X + all 3 W in one launch) ----------
__global__ void cvt_all(const float4* __restrict__ x,
                        const float4* __restrict__ wq,
                        const float4* __restrict__ wk,
                        const float4* __restrict__ wv) {
    int bid = blockIdx.x;
    const float4* src;
    __half2* dst;
    int i;
    if (bid < 8192) {                       // X: 2097152 float4s
        src = x; dst = (__half2*)g_Xh;
        i = bid * 256 + threadIdx.x;
    } else {                                // W[z]: 262144 float4s each
        int r = bid - 8192;
        int z = r >> 10;
        src = (z == 0) ? wq : (z == 1) ? wk : wv;
        dst = (__half2*)g_Wh[z];
        i = (r & 1023) * 256 + threadIdx.x;
    }
    float4 v = src[i];
    dst[2 * i + 0] = __floats2half2_rn(v.x, v.y);
    dst[2 * i + 1] = __floats2half2_rn(v.z, v.w);
}

// ---------------- fused QKV projection (3-stage pipeline) -------------------
// BK=64, CTA tile 128x128, 8 warps (warp tile 64x32), occupancy 2.
// V (z==2) epilogue goes through a smem [n][m] transpose so g_Vt stores are
// fully coalesced uint4 writes (was: 64 scattered 2B stores per thread).
// smem: A stages [3][128][72]h at 0 (55296 B), B stages at 55296. 110592 B.
#define QKV_SMEM 110592
__global__ __launch_bounds__(256, 2) void qkv_gemm(const float* __restrict__ bq,
                                                   const float* __restrict__ bk,
                                                   const float* __restrict__ bv) {
    extern __shared__ char qsm[];

    const int z  = blockIdx.z;
    const __half* W    = g_Wh[z];
    const float*  bias = (z == 0) ? bq : (z == 1) ? bk : bv;
    const int m0 = blockIdx.y * 128;
    const int n0 = blockIdx.x * 128;

    const int t    = threadIdx.x;
    const int warp = t >> 5, lane = t & 31;
    const int wm = warp & 1, wn = warp >> 1;

    auto load_st = [&](int st, int kb) {
#pragma unroll
        for (int i = 0; i < 4; i++) {
            int idx = t + i * 256;              // 1024 chunks of 16B per tile
            int row = idx >> 3, c = idx & 7;
            cpa16(smem_u32(qsm + st * 18432 + row * 144 + c * 16),
                  g_Xh + (size_t)(m0 + row) * 1024 + kb * 64 + c * 8);
            cpa16(smem_u32(qsm + 55296 + st * 18432 + row * 144 + c * 16),
                  W + (size_t)(n0 + row) * 1024 + kb * 64 + c * 8);
        }
    };

    float acc[4][4][4];
#pragma unroll
    for (int i = 0; i < 4; i++)
#pragma unroll
        for (int j = 0; j < 4; j++)
#pragma unroll
            for (int k = 0; k < 4; k++) acc[i][j][k] = 0.f;

    const uint32_t aOff = (uint32_t)(wm * 64 + (lane & 15)) * 144 + (lane >> 4) * 16;
    const uint32_t bOff = (uint32_t)(wn * 32 + (lane & 7) + ((lane >> 4) & 1) * 8) * 144
                        + ((lane >> 3) & 1) * 16;

    load_st(0, 0);
    CP_COMMIT();
    load_st(1, 1);
    CP_COMMIT();

    int st = 0;
    for (int kb = 0; kb < 16; kb++) {
        CP_WAIT(1);
        __syncthreads();
        if (kb + 2 < 16) load_st((kb + 2) % 3, kb + 2);
        CP_COMMIT();

        const uint32_t aAddr = smem_u32(qsm) + st * 18432 + aOff;
        const uint32_t bAddr = smem_u32(qsm) + 55296 + st * 18432 + bOff;
        st = (st == 2) ? 0 : st + 1;
#pragma unroll
        for (int kc = 0; kc < 4; kc++) {
            uint32_t a[4][4], b[2][4];
#pragma unroll
            for (int mt = 0; mt < 4; mt++) ldm4(a[mt], aAddr + kc * 32 + mt * 16 * 144);
#pragma unroll
            for (int np = 0; np < 2; np++) ldm4(b[np], bAddr + kc * 32 + np * 16 * 144);
#pragma unroll
            for (int mt = 0; mt < 4; mt++)
#pragma unroll
                for (int nt = 0; nt < 4; nt++)
                    mma16816(acc[mt][nt], a[mt], b[nt >> 1] + (nt & 1) * 2);
        }
    }

    if (z < 2) {
        // Q/K epilogue: bias + direct head-major store
        __half* dst = (z == 0) ? g_Q : g_K;
#pragma unroll
        for (int mt = 0; mt < 4; mt++) {
            int m  = m0 + wm * 64 + mt * 16 + (lane >> 2);
            int bb = m >> 11;
            int s  = m & 2047;
#pragma unroll
            for (int nt = 0; nt < 4; nt++) {
                int n  = n0 + wn * 32 + nt * 8 + (lane & 3) * 2;
                int h  = n >> 6, hd = n & 63;
                int bh = bb * 16 + h;
                float bs0 = bias[n], bs1 = bias[n + 1];
                *(__half2*)&dst[((size_t)bh * 2048 + s    ) * 64 + hd] =
                    __floats2half2_rn(acc[mt][nt][0] + bs0, acc[mt][nt][1] + bs1);
                *(__half2*)&dst[((size_t)bh * 2048 + s + 8) * 64 + hd] =
                    __floats2half2_rn(acc[mt][nt][2] + bs0, acc[mt][nt][3] + bs1);
            }
        }
    } else {
        // V epilogue: stage through smem as [n][m] (pad 136 halves/row),
        // then fully-coalesced uint4 stores along s into g_Vt.
        __syncthreads();                       // all warps done with stage smem
        __half* Vs = (__half*)qsm;             // 128 x 136 halves = 34816 B
#pragma unroll
        for (int mt = 0; mt < 4; mt++) {
            int ml = wm * 64 + mt * 16 + (lane >> 2);
#pragma unroll
            for (int nt = 0; nt < 4; nt++) {
                int nl = wn * 32 + nt * 8 + (lane & 3) * 2;
                float bs0 = bias[n0 + nl], bs1 = bias[n0 + nl + 1];
                Vs[(nl    ) * 136 + ml    ] = __float2half_rn(acc[mt][nt][0] + bs0);
                Vs[(nl + 1) * 136 + ml    ] = __float2half_rn(acc[mt][nt][1] + bs1);
                Vs[(nl    ) * 136 + ml + 8] = __float2half_rn(acc[mt][nt][2] + bs0);
                Vs[(nl + 1) * 136 + ml + 8] = __float2half_rn(acc[mt][nt][3] + bs1);
            }
        }
        __syncthreads();
        const int bb = m0 >> 11;               // tile fits in one batch
        const int nl = t >> 1;                 // local n (0..127)
        const int mh = (t & 1) * 64;           // m half (0 or 64)
        const int ng = n0 + nl;
        const int h  = ng >> 6, hd = ng & 63;
        const size_t dstBase = ((size_t)(bb * 16 + h) * 64 + hd) * 2048 + ((m0 + mh) & 2047);
#pragma unroll
        for (int j = 0; j < 8; j++) {
            uint4 v = *(const uint4*)&Vs[nl * 136 + mh + j * 8];
            *(uint4*)&g_Vt[dstBase + j * 8] = v;
        }
    }
}

// ---------------- FlashAttention (R10 best: 4 warps x 32 q-rows) ------------
// 128 q-rows / CTA, 4 warps of TWO m-tiles each; 64-key tiles, 3-stage
// cp.async (wait_group 1). Shift-free fp16x2 softmax; softmax of score-chunk
// kc is interleaved with the PV MMAs of chunk kc.
// smem layout (bytes):
//   Qs [128][72] half : 0      .. 18432
//   Ks [3][64][72]    : 18432  .. 46080   (stage = 9216)
//   Vs [3][64][72]    : 46080  .. 73728
//   mk [3][64] float  : 73728  .. 74496
#define ATTN_SMEM 74496
__global__ __launch_bounds__(128, 2) void attn_kernel(const float* __restrict__ mask,
                                                      float* __restrict__ out) {
    extern __shared__ char sm[];
    __half (*Qs)[72] = (__half(*)[72])sm;
    char* ksBase = sm + 18432;
    char* vsBase = sm + 46080;
    float* mkBase = (float*)(sm + 73728);

    const int bh = blockIdx.y;
    const int q0 = blockIdx.x * 128;
    const int b  = bh >> 4, h = bh & 15;
    const int t = threadIdx.x, warp = t >> 5, lane = t & 31;
    const __half2 clamp14 = __floats2half2_rn(14.f, 14.f);

    auto load_kv = [&](int st, int k0) {
#pragma unroll
        for (int i = 0; i < 4; i++) {
            int idx = t + i * 128;           // 512 chunks of 16B per tile
            int row = idx >> 3, cb = idx & 7;
            cpa16(smem_u32(ksBase + st * 9216 + row * 144 + cb * 16),
                  &g_K[((size_t)bh * 2048 + k0 + row) * 64 + cb * 8]);
            cpa16(smem_u32(vsBase + st * 9216 + row * 144 + cb * 16),
                  &g_Vt[((size_t)bh * 64 + row) * 2048 + k0 + cb * 8]);
        }
        if (t < 64)
            mkBase[st * 64 + t] = mask[b * 2048 + k0 + t] * LOG2E;
    };

    load_kv(0, 0);
    CP_COMMIT();
    load_kv(1, 64);
    CP_COMMIT();

#pragma unroll
    for (int i = 0; i < 8; i++) {
        int idx = t + i * 128;              // 1024 chunks for the 128x64 Q tile
        int row = idx >> 3, c8 = (idx & 7) * 8;
        *(uint4*)&Qs[row][c8] =
            *(const uint4*)&g_Q[((size_t)bh * 2048 + q0 + row) * 64 + c8];
    }
    __syncthreads();

    // Q fragments: 2 m-tiles x 4 k-chunks
    uint32_t qa[2][4][4];
#pragma unroll
    for (int mt = 0; mt < 2; mt++) {
        uint32_t qAddr = smem_u32(&Qs[warp * 32 + mt * 16 + (lane & 15)][(lane >> 4) * 8]);
#pragma unroll
        for (int ks = 0; ks < 4; ks++) ldm4(qa[mt][ks], qAddr + ks * 32);
    }

    const uint32_t kOff = ((lane & 7) + ((lane >> 4) & 1) * 8) * 144 + ((lane >> 3) & 1) * 16;
    const uint32_t kA0 = smem_u32(ksBase) + kOff;
    const uint32_t vA0 = smem_u32(vsBase) + kOff;

    float o[2][8][4];
#pragma unroll
    for (int mt = 0; mt < 2; mt++)
#pragma unroll
        for (int i = 0; i < 8; i++)
#pragma unroll
            for (int j = 0; j < 4; j++) o[mt][i][j] = 0.f;
    float l00 = 0.f, l01 = 0.f, l10 = 0.f, l11 = 0.f;

    int st = 0;
    for (int kt = 0; kt < 32; kt++) {
        CP_WAIT(1);                    // stage kt resident; kt+1 may be in flight
        __syncthreads();               // stage (kt+2)%3 fully consumed
        if (kt + 2 < 32) load_kv((kt + 2) % 3, (kt + 2) * 64);
        CP_COMMIT();

        const uint32_t kA = kA0 + st * 9216;
        const uint32_t vA = vA0 + st * 9216;
        const float* mk = mkBase + st * 64;
        st = (st == 2) ? 0 : st + 1;

        // scores: 32 q-rows x 64 keys; K fragments reused for both m-tiles
        float sc[2][8][4];
#pragma unroll
        for (int mt = 0; mt < 2; mt++)
#pragma unroll
            for (int nt = 0; nt < 8; nt++)
#pragma unroll
                for (int j = 0; j < 4; j++) sc[mt][nt][j] = 0.f;
#pragma unroll
        for (int ks = 0; ks < 4; ks++) {
#pragma unroll
            for (int np = 0; np < 4; np++) {
                uint32_t kf[4];
                ldm4(kf, kA + np * 16 * 144 + ks * 32);
#pragma unroll
                for (int mt = 0; mt < 2; mt++) {
                    mma16816(sc[mt][2*np    ], qa[mt][ks], kf);
                    mma16816(sc[mt][2*np + 1], qa[mt][ks], kf + 2);
                }
            }
        }

        // chunk-interleaved softmax + PV
#pragma unroll
        for (int kc = 0; kc < 4; kc++) {
            uint32_t ph[2][4];
#pragma unroll
            for (int mt = 0; mt < 2; mt++) {
                float lp0 = 0.f, lp1 = 0.f;
#pragma unroll
                for (int u = 0; u < 2; u++) {
                    int nt = 2 * kc + u;
                    int key = nt * 8 + (lane & 3) * 2;
                    float mk0v = mk[key], mk1v = mk[key + 1];
                    float s0 = fmaf(sc[mt][nt][0], SCL, mk0v);
                    float s1 = fmaf(sc[mt][nt][1], SCL, mk1v);
                    float s2 = fmaf(sc[mt][nt][2], SCL, mk0v);
                    float s3 = fmaf(sc[mt][nt][3], SCL, mk1v);
                    ph[mt][2*u    ] = h2ex2(s0, s1, clamp14);
                    ph[mt][2*u + 1] = h2ex2(s2, s3, clamp14);
                    float2 f0 = __half22float2(*reinterpret_cast<__half2*>(&ph[mt][2*u]));
                    float2 f1 = __half22float2(*reinterpret_cast<__half2*>(&ph[mt][2*u+1]));
                    lp0 += f0.x + f0.y;
                    lp1 += f1.x + f1.y;
                }
                if (mt == 0) { l00 += lp0; l01 += lp1; }
                else         { l10 += lp0; l11 += lp1; }
            }
#pragma unroll
            for (int hp = 0; hp < 4; hp++) {
                uint32_t vf[4];
                ldm4(vf, vA + hp * 16 * 144 + kc * 32);
#pragma unroll
                for (int mt = 0; mt < 2; mt++) {
                    mma16816(o[mt][2*hp    ], ph[mt], vf);
                    mma16816(o[mt][2*hp + 1], ph[mt], vf + 2);
                }
            }
        }
    }

    // epilogue: one cross-lane reduction, normalize, store fp32 [B,S,D]
    l00 += __shfl_xor_sync(0xffffffffu, l00, 1);
    l00 += __shfl_xor_sync(0xffffffffu, l00, 2);
    l01 += __shfl_xor_sync(0xffffffffu, l01, 1);
    l01 += __shfl_xor_sync(0xffffffffu, l01, 2);
    l10 += __shfl_xor_sync(0xffffffffu, l10, 1);
    l10 += __shfl_xor_sync(0xffffffffu, l10, 2);
    l11 += __shfl_xor_sync(0xffffffffu, l11, 1);
    l11 += __shfl_xor_sync(0xffffffffu, l11, 2);
    const int cb = h * 64 + (lane & 3) * 2;
#pragma unroll
    for (int mt = 0; mt < 2; mt++) {
        float rl0 = 1.f / (mt ? l10 : l00);
        float rl1 = 1.f / (mt ? l11 : l01);
        int s0 = q0 + warp * 32 + mt * 16 + (lane >> 2);
#pragma unroll
        for (int ht = 0; ht < 8; ht++) {
            int c = cb + ht * 8;
            float2 v0 = make_float2(o[mt][ht][0] * rl0, o[mt][ht][1] * rl0);
            float2 v1 = make_float2(o[mt][ht][2] * rl1, o[mt][ht][3] * rl1);
            *(float2*)&out[((size_t)b * 2048 + s0    ) * 1024 + c] = v0;
            *(float2*)&out[((size_t)b * 2048 + s0 + 8) * 1024 + c] = v1;
        }
    }
}

// ---------------- launch -----------------------------------------------------
extern "C" void kernel_launch(void* const* d_in, const int* in_sizes, int n_in,
                              void* d_out, int out_size) {
    const float* hidden = (const float*)d_in[0];
    const float* mask   = (const float*)d_in[1];
    const float* Wq     = (const float*)d_in[2];
    const float* bq     = (const float*)d_in[3];
    const float* Wk     = (const float*)d_in[4];
    const float* bk     = (const float*)d_in[5];
    const float* Wv     = (const float*)d_in[6];
    const float* bv     = (const float*)d_in[7];
    float* out = (float*)d_out;

    cudaFuncSetAttribute(qkv_gemm, cudaFuncAttributeMaxDynamicSharedMemorySize, QKV_SMEM);
    cudaFuncSetAttribute(attn_kernel, cudaFuncAttributeMaxDynamicSharedMemorySize, ATTN_SMEM);

    cvt_all<<<11264, 256>>>((const float4*)hidden, (const float4*)Wq,
                            (const float4*)Wk, (const float4*)Wv);

    dim3 g1(8, 64, 3);      // N-blocks, M-blocks, {Q,K,V}
    qkv_gemm<<<g1, 256, QKV_SMEM>>>(bq, bk, bv);

    dim3 g2(16, 64);        // q-tiles (128 rows), B*H
    attn_kernel<<<g2, 128, ATTN_SMEM>>>(mask, out);
}

// round 14
// speedup vs baseline: 1.0278x; 1.0228x over previous
#include <cuda_runtime.h>
#include <cuda_fp16.h>
#include <stdint.h>

// Problem dims (fixed): B=4, S=2048, D=1024, H=16, HD=64
#define LOG2E 1.4426950408889634f
#define SCL   (0.125f * 1.4426950408889634f)   // 1/sqrt(64) * log2(e)

// ---------------- device scratch (static: allocation-free at launch) -------
__device__ __half g_Xh[8192 * 1024];          // hidden in fp16        (16 MB)
__device__ __half g_Wh[3][1024 * 1024];       // Wq/Wk/Wv in fp16      ( 6 MB)
__device__ __half g_Q [64 * 2048 * 64];       // Q  [bh][s][hd]        (16 MB)
__device__ __half g_K [64 * 2048 * 64];       // K  [bh][s][hd]        (16 MB)
__device__ __half g_Vt[64 * 64 * 2048];       // V^T [bh][hd][s]       (16 MB)

// ---------------- helpers ----------------------------------------------------
__device__ __forceinline__ uint32_t smem_u32(const void* p) {
    return (uint32_t)__cvta_generic_to_shared(p);
}
__device__ __forceinline__ void ldm4(uint32_t* r, uint32_t a) {
    asm volatile("ldmatrix.sync.aligned.m8n8.x4.shared.b16 {%0,%1,%2,%3}, [%4];"
                 : "=r"(r[0]), "=r"(r[1]), "=r"(r[2]), "=r"(r[3]) : "r"(a));
}
__device__ __forceinline__ void mma16816(float* c, const uint32_t* a, const uint32_t* b) {
    asm volatile(
        "mma.sync.aligned.m16n8k16.row.col.f32.f16.f16.f32 "
        "{%0,%1,%2,%3}, {%4,%5,%6,%7}, {%8,%9}, {%0,%1,%2,%3};"
        : "+f"(c[0]), "+f"(c[1]), "+f"(c[2]), "+f"(c[3])
        : "r"(a[0]), "r"(a[1]), "r"(a[2]), "r"(a[3]), "r"(b[0]), "r"(b[1]));
}
__device__ __forceinline__ void cpa16(uint32_t dst, const void* src) {
    asm volatile("cp.async.cg.shared.global [%0], [%1], 16;" :: "r"(dst), "l"(src));
}
#define CP_COMMIT() asm volatile("cp.async.commit_group;")
#define CP_WAIT(n)  asm volatile("cp.async.wait_group %0;" :: "n"(n))

__device__ __forceinline__ uint32_t h2ex2(float a, float b, __half2 clamp) {
    __half2 h = __hmin2(__floats2half2_rn(a, b), clamp);
    uint32_t r, x = *reinterpret_cast<uint32_t*>(&h);
    asm volatile("ex2.approx.f16x2 %0, %1;" : "=r"(r) : "r"(x));
    return r;
}

// ---------------- fp32 -> fp16 convert (X + all 3 W in one launch) ----------
__global__ void cvt_all(const float4* __restrict__ x,
                        const float4* __restrict__ wq,
                        const float4* __restrict__ wk,
                        const float4* __restrict__ wv) {
    int bid = blockIdx.x;
    const float4* src;
    __half2* dst;
    int i;
    if (bid < 8192) {                       // X: 2097152 float4s
        src = x; dst = (__half2*)g_Xh;
        i = bid * 256 + threadIdx.x;
    } else {                                // W[z]: 262144 float4s each
        int r = bid - 8192;
        int z = r >> 10;
        src = (z == 0) ? wq : (z == 1) ? wk : wv;
        dst = (__half2*)g_Wh[z];
        i = (r & 1023) * 256 + threadIdx.x;
    }
    float4 v = src[i];
    dst[2 * i + 0] = __floats2half2_rn(v.x, v.y);
    dst[2 * i + 1] = __floats2half2_rn(v.z, v.w);
}

// ---------------- fused QKV projection (R10 winner, reverted) ---------------
// BK=64, CTA tile 128x128, 8 warps (warp tile 64x32), occupancy 2.
// 3-stage cp.async ring with wait_group 1.
// smem: A stages [3][128][72]h at 0 (55296 B), B stages at 55296. 110592 B.
#define QKV_SMEM 110592
__global__ __launch_bounds__(256, 2) void qkv_gemm(const float* __restrict__ bq,
                                                   const float* __restrict__ bk,
                                                   const float* __restrict__ bv) {
    extern __shared__ char qsm[];

    const int z  = blockIdx.z;
    const __half* W    = g_Wh[z];
    const float*  bias = (z == 0) ? bq : (z == 1) ? bk : bv;
    const int m0 = blockIdx.y * 128;
    const int n0 = blockIdx.x * 128;

    const int t    = threadIdx.x;
    const int warp = t >> 5, lane = t & 31;
    const int wm = warp & 1, wn = warp >> 1;

    auto load_st = [&](int st, int kb) {
#pragma unroll
        for (int i = 0; i < 4; i++) {
            int idx = t + i * 256;              // 1024 chunks of 16B per tile
            int row = idx >> 3, c = idx & 7;
            cpa16(smem_u32(qsm + st * 18432 + row * 144 + c * 16),
                  g_Xh + (size_t)(m0 + row) * 1024 + kb * 64 + c * 8);
            cpa16(smem_u32(qsm + 55296 + st * 18432 + row * 144 + c * 16),
                  W + (size_t)(n0 + row) * 1024 + kb * 64 + c * 8);
        }
    };

    float acc[4][4][4];
#pragma unroll
    for (int i = 0; i < 4; i++)
#pragma unroll
        for (int j = 0; j < 4; j++)
#pragma unroll
            for (int k = 0; k < 4; k++) acc[i][j][k] = 0.f;

    const uint32_t aOff = (uint32_t)(wm * 64 + (lane & 15)) * 144 + (lane >> 4) * 16;
    const uint32_t bOff = (uint32_t)(wn * 32 + (lane & 7) + ((lane >> 4) & 1) * 8) * 144
                        + ((lane >> 3) & 1) * 16;

    load_st(0, 0);
    CP_COMMIT();
    load_st(1, 1);
    CP_COMMIT();

    int st = 0;
    for (int kb = 0; kb < 16; kb++) {
        CP_WAIT(1);
        __syncthreads();
        if (kb + 2 < 16) load_st((kb + 2) % 3, kb + 2);
        CP_COMMIT();

        const uint32_t aAddr = smem_u32(qsm) + st * 18432 + aOff;
        const uint32_t bAddr = smem_u32(qsm) + 55296 + st * 18432 + bOff;
        st = (st == 2) ? 0 : st + 1;
#pragma unroll
        for (int kc = 0; kc < 4; kc++) {
            uint32_t a[4][4], b[2][4];
#pragma unroll
            for (int mt = 0; mt < 4; mt++) ldm4(a[mt], aAddr + kc * 32 + mt * 16 * 144);
#pragma unroll
            for (int np = 0; np < 2; np++) ldm4(b[np], bAddr + kc * 32 + np * 16 * 144);
#pragma unroll
            for (int mt = 0; mt < 4; mt++)
#pragma unroll
                for (int nt = 0; nt < 4; nt++)
                    mma16816(acc[mt][nt], a[mt], b[nt >> 1] + (nt & 1) * 2);
        }
    }

    // epilogue: bias + store into head-major scratch (fp16)
#pragma unroll
    for (int mt = 0; mt < 4; mt++) {
        int m  = m0 + wm * 64 + mt * 16 + (lane >> 2);
        int bb = m >> 11;
        int s  = m & 2047;
#pragma unroll
        for (int nt = 0; nt < 4; nt++) {
            int n  = n0 + wn * 32 + nt * 8 + (lane & 3) * 2;
            int h  = n >> 6, hd = n & 63;
            int bh = bb * 16 + h;
            float bs0 = bias[n], bs1 = bias[n + 1];
            float v00 = acc[mt][nt][0] + bs0, v01 = acc[mt][nt][1] + bs1;
            float v10 = acc[mt][nt][2] + bs0, v11 = acc[mt][nt][3] + bs1;
            if (z < 2) {
                __half* dst = (z == 0) ? g_Q : g_K;
                *(__half2*)&dst[((size_t)bh * 2048 + s    ) * 64 + hd] = __floats2half2_rn(v00, v01);
                *(__half2*)&dst[((size_t)bh * 2048 + s + 8) * 64 + hd] = __floats2half2_rn(v10, v11);
            } else {
                g_Vt[((size_t)bh * 64 + hd    ) * 2048 + s    ] = __float2half_rn(v00);
                g_Vt[((size_t)bh * 64 + hd + 1) * 2048 + s    ] = __float2half_rn(v01);
                g_Vt[((size_t)bh * 64 + hd    ) * 2048 + s + 8] = __float2half_rn(v10);
                g_Vt[((size_t)bh * 64 + hd + 1) * 2048 + s + 8] = __float2half_rn(v11);
            }
        }
    }
}

// ---------------- FlashAttention (128-key stages, smem-resident mask) -------
// 128 q-rows / CTA, 4 warps of TWO m-tiles each. 128-key stages processed as
// two 64-key halves with the proven R10 inner block (identical registers).
// 2-stage cp.async double buffer (16 barrier windows instead of 32).
// Mask row (2048 floats * LOG2E) preloaded to smem ONCE — no per-iteration
// mask LDG/STS stalls in the mainloop.
// smem layout (bytes):
//   Qs [128][72] half  : 0      .. 18432
//   Ks [2][128][72]    : 18432  .. 55296   (stage = 18432)
//   Vs [2][64][136]    : 55296  .. 90112   (stage = 17408, 272B rows)
//   maskSm [2048] f32  : 90112  .. 98304
#define ATTN_SMEM 98304
__global__ __launch_bounds__(128, 2) void attn_kernel(const float* __restrict__ mask,
                                                      float* __restrict__ out) {
    extern __shared__ char sm[];
    __half (*Qs)[72] = (__half(*)[72])sm;
    char* ksBase = sm + 18432;
    char* vsBase = sm + 55296;
    float* maskSm = (float*)(sm + 90112);

    const int bh = blockIdx.y;
    const int q0 = blockIdx.x * 128;
    const int b  = bh >> 4, h = bh & 15;
    const int t = threadIdx.x, warp = t >> 5, lane = t & 31;
    const __half2 clamp14 = __floats2half2_rn(14.f, 14.f);

    // stage loader: 128-key K tile (128x72h rows) + V^T tile (64x136h rows)
    auto load_kv = [&](int st, int k0) {
#pragma unroll
        for (int i = 0; i < 8; i++) {
            int idx = t + i * 128;           // K: 1024 chunks of 16B
            int row = idx >> 3, cb = idx & 7;
            cpa16(smem_u32(ksBase + st * 18432 + row * 144 + cb * 16),
                  &g_K[((size_t)bh * 2048 + k0 + row) * 64 + cb * 8]);
        }
#pragma unroll
        for (int i = 0; i < 8; i++) {
            int idx = t + i * 128;           // V: 1024 chunks of 16B
            int row = idx >> 4, cb = idx & 15;
            cpa16(smem_u32(vsBase + st * 17408 + row * 272 + cb * 16),
                  &g_Vt[((size_t)bh * 64 + row) * 2048 + k0 + cb * 8]);
        }
    };

    load_kv(0, 0);
    CP_COMMIT();

    // one-time mask preload (scaled by LOG2E); LDGs overlap Q tile loads
#pragma unroll
    for (int i = 0; i < 16; i++)
        maskSm[t + i * 128] = mask[b * 2048 + t + i * 128] * LOG2E;

#pragma unroll
    for (int i = 0; i < 8; i++) {
        int idx = t + i * 128;              // 1024 chunks for the 128x64 Q tile
        int row = idx >> 3, c8 = (idx & 7) * 8;
        *(uint4*)&Qs[row][c8] =
            *(const uint4*)&g_Q[((size_t)bh * 2048 + q0 + row) * 64 + c8];
    }
    __syncthreads();

    // Q fragments: 2 m-tiles x 4 k-chunks
    uint32_t qa[2][4][4];
#pragma unroll
    for (int mt = 0; mt < 2; mt++) {
        uint32_t qAddr = smem_u32(&Qs[warp * 32 + mt * 16 + (lane & 15)][(lane >> 4) * 8]);
#pragma unroll
        for (int ks = 0; ks < 4; ks++) ldm4(qa[mt][ks], qAddr + ks * 32);
    }

    const uint32_t kOff = ((lane & 7) + ((lane >> 4) & 1) * 8) * 144 + ((lane >> 3) & 1) * 16;
    const uint32_t vOff = ((lane & 7) + ((lane >> 4) & 1) * 8) * 272 + ((lane >> 3) & 1) * 16;
    const uint32_t kA0 = smem_u32(ksBase) + kOff;
    const uint32_t vA0 = smem_u32(vsBase) + vOff;

    float o[2][8][4];
#pragma unroll
    for (int mt = 0; mt < 2; mt++)
#pragma unroll
        for (int i = 0; i < 8; i++)
#pragma unroll
            for (int j = 0; j < 4; j++) o[mt][i][j] = 0.f;
    float l00 = 0.f, l01 = 0.f, l10 = 0.f, l11 = 0.f;

    for (int kt = 0; kt < 16; kt++) {
        CP_WAIT(0);                    // stage kt resident
        __syncthreads();               // stage kt-1 fully consumed by all warps
        if (kt + 1 < 16) load_kv((kt + 1) & 1, (kt + 1) * 128);
        CP_COMMIT();

        const int stg = kt & 1;
#pragma unroll
        for (int hh = 0; hh < 2; hh++) {
            const uint32_t kA = kA0 + stg * 18432 + hh * 64 * 144;
            const uint32_t vA = vA0 + stg * 17408 + hh * 128;   // 64 keys * 2B
            const float* mk = maskSm + kt * 128 + hh * 64;

            // scores: 32 q-rows x 64 keys; K fragments reused for both m-tiles
            float sc[2][8][4];
#pragma unroll
            for (int mt = 0; mt < 2; mt++)
#pragma unroll
                for (int nt = 0; nt < 8; nt++)
#pragma unroll
                    for (int j = 0; j < 4; j++) sc[mt][nt][j] = 0.f;
#pragma unroll
            for (int ks = 0; ks < 4; ks++) {
#pragma unroll
                for (int np = 0; np < 4; np++) {
                    uint32_t kf[4];
                    ldm4(kf, kA + np * 16 * 144 + ks * 32);
#pragma unroll
                    for (int mt = 0; mt < 2; mt++) {
                        mma16816(sc[mt][2*np    ], qa[mt][ks], kf);
                        mma16816(sc[mt][2*np + 1], qa[mt][ks], kf + 2);
                    }
                }
            }

            // chunk-interleaved softmax + PV
#pragma unroll
            for (int kc = 0; kc < 4; kc++) {
                uint32_t ph[2][4];
#pragma unroll
                for (int mt = 0; mt < 2; mt++) {
                    float lp0 = 0.f, lp1 = 0.f;
#pragma unroll
                    for (int u = 0; u < 2; u++) {
                        int nt = 2 * kc + u;
                        int key = nt * 8 + (lane & 3) * 2;
                        float mk0v = mk[key], mk1v = mk[key + 1];
                        float s0 = fmaf(sc[mt][nt][0], SCL, mk0v);
                        float s1 = fmaf(sc[mt][nt][1], SCL, mk1v);
                        float s2 = fmaf(sc[mt][nt][2], SCL, mk0v);
                        float s3 = fmaf(sc[mt][nt][3], SCL, mk1v);
                        ph[mt][2*u    ] = h2ex2(s0, s1, clamp14);
                        ph[mt][2*u + 1] = h2ex2(s2, s3, clamp14);
                        float2 f0 = __half22float2(*reinterpret_cast<__half2*>(&ph[mt][2*u]));
                        float2 f1 = __half22float2(*reinterpret_cast<__half2*>(&ph[mt][2*u+1]));
                        lp0 += f0.x + f0.y;
                        lp1 += f1.x + f1.y;
                    }
                    if (mt == 0) { l00 += lp0; l01 += lp1; }
                    else         { l10 += lp0; l11 += lp1; }
                }
#pragma unroll
                for (int hp = 0; hp < 4; hp++) {
                    uint32_t vf[4];
                    ldm4(vf, vA + hp * 16 * 272 + kc * 32);
#pragma unroll
                    for (int mt = 0; mt < 2; mt++) {
                        mma16816(o[mt][2*hp    ], ph[mt], vf);
                        mma16816(o[mt][2*hp + 1], ph[mt], vf + 2);
                    }
                }
            }
        }
    }

    // epilogue: one cross-lane reduction, normalize, store fp32 [B,S,D]
    l00 += __shfl_xor_sync(0xffffffffu, l00, 1);
    l00 += __shfl_xor_sync(0xffffffffu, l00, 2);
    l01 += __shfl_xor_sync(0xffffffffu, l01, 1);
    l01 += __shfl_xor_sync(0xffffffffu, l01, 2);
    l10 += __shfl_xor_sync(0xffffffffu, l10, 1);
    l10 += __shfl_xor_sync(0xffffffffu, l10, 2);
    l11 += __shfl_xor_sync(0xffffffffu, l11, 1);
    l11 += __shfl_xor_sync(0xffffffffu, l11, 2);
    const int cb = h * 64 + (lane & 3) * 2;
#pragma unroll
    for (int mt = 0; mt < 2; mt++) {
        float rl0 = 1.f / (mt ? l10 : l00);
        float rl1 = 1.f / (mt ? l11 : l01);
        int s0 = q0 + warp * 32 + mt * 16 + (lane >> 2);
#pragma unroll
        for (int ht = 0; ht < 8; ht++) {
            int c = cb + ht * 8;
            float2 v0 = make_float2(o[mt][ht][0] * rl0, o[mt][ht][1] * rl0);
            float2 v1 = make_float2(o[mt][ht][2] * rl1, o[mt][ht][3] * rl1);
            *(float2*)&out[((size_t)b * 2048 + s0    ) * 1024 + c] = v0;
            *(float2*)&out[((size_t)b * 2048 + s0 + 8) * 1024 + c] = v1;
        }
    }
}

// ---------------- launch -----------------------------------------------------
extern "C" void kernel_launch(void* const* d_in, const int* in_sizes, int n_in,
                              void* d_out, int out_size) {
    const float* hidden = (const float*)d_in[0];
    const float* mask   = (const float*)d_in[1];
    const float* Wq     = (const float*)d_in[2];
    const float* bq     = (const float*)d_in[3];
    const float* Wk     = (const float*)d_in[4];
    const float* bk     = (const float*)d_in[5];
    const float* Wv     = (const float*)d_in[6];
    const float* bv     = (const float*)d_in[7];
    float* out = (float*)d_out;

    cudaFuncSetAttribute(qkv_gemm, cudaFuncAttributeMaxDynamicSharedMemorySize, QKV_SMEM);
    cudaFuncSetAttribute(attn_kernel, cudaFuncAttributeMaxDynamicSharedMemorySize, ATTN_SMEM);

    cvt_all<<<11264, 256>>>((const float4*)hidden, (const float4*)Wq,
                            (const float4*)Wk, (const float4*)Wv);

    dim3 g1(8, 64, 3);      // N-blocks, M-blocks, {Q,K,V}
    qkv_gemm<<<g1, 256, QKV_SMEM>>>(bq, bk, bv);

    dim3 g2(16, 64);        // q-tiles (128 rows), B*H
    attn_kernel<<<g2, 128, ATTN_SMEM>>>(mask, out);
}

// round 15
// speedup vs baseline: 1.0350x; 1.0069x over previous
#include <cuda_runtime.h>
#include <cuda_fp16.h>
#include <stdint.h>

// Problem dims (fixed): B=4, S=2048, D=1024, H=16, HD=64
#define LOG2E 1.4426950408889634f
#define SCL   (0.125f * 1.4426950408889634f)   // 1/sqrt(64) * log2(e)

// ---------------- device scratch (static: allocation-free at launch) -------
__device__ __half g_Xh[8192 * 1024];          // hidden in fp16        (16 MB)
__device__ __half g_Wh[3][1024 * 1024];       // Wq/Wk/Wv in fp16      ( 6 MB)
__device__ __half g_Q [64 * 2048 * 64];       // Q  [bh][s][hd]        (16 MB)
__device__ __half g_K [64 * 2048 * 64];       // K  [bh][s][hd]        (16 MB)
__device__ __half g_Vt[64 * 64 * 2048];       // V^T [bh][hd][s]       (16 MB)

// ---------------- helpers ----------------------------------------------------
__device__ __forceinline__ uint32_t smem_u32(const void* p) {
    return (uint32_t)__cvta_generic_to_shared(p);
}
__device__ __forceinline__ void ldm4(uint32_t* r, uint32_t a) {
    asm volatile("ldmatrix.sync.aligned.m8n8.x4.shared.b16 {%0,%1,%2,%3}, [%4];"
                 : "=r"(r[0]), "=r"(r[1]), "=r"(r[2]), "=r"(r[3]) : "r"(a));
}
__device__ __forceinline__ void mma16816(float* c, const uint32_t* a, const uint32_t* b) {
    asm volatile(
        "mma.sync.aligned.m16n8k16.row.col.f32.f16.f16.f32 "
        "{%0,%1,%2,%3}, {%4,%5,%6,%7}, {%8,%9}, {%0,%1,%2,%3};"
        : "+f"(c[0]), "+f"(c[1]), "+f"(c[2]), "+f"(c[3])
        : "r"(a[0]), "r"(a[1]), "r"(a[2]), "r"(a[3]), "r"(b[0]), "r"(b[1]));
}
__device__ __forceinline__ void cpa16(uint32_t dst, const void* src) {
    asm volatile("cp.async.cg.shared.global [%0], [%1], 16;" :: "r"(dst), "l"(src));
}
#define CP_COMMIT() asm volatile("cp.async.commit_group;")
#define CP_WAIT(n)  asm volatile("cp.async.wait_group %0;" :: "n"(n))

__device__ __forceinline__ uint32_t h2ex2(float a, float b, __half2 clamp) {
    __half2 h = __hmin2(__floats2half2_rn(a, b), clamp);
    uint32_t r, x = *reinterpret_cast<uint32_t*>(&h);
    asm volatile("ex2.approx.f16x2 %0, %1;" : "=r"(r) : "r"(x));
    return r;
}

// ---------------- fp32 -> fp16 convert (X + all 3 W in one launch) ----------
__global__ void cvt_all(const float4* __restrict__ x,
                        const float4* __restrict__ wq,
                        const float4* __restrict__ wk,
                        const float4* __restrict__ wv) {
    int bid = blockIdx.x;
    const float4* src;
    __half2* dst;
    int i;
    if (bid < 8192) {                       // X: 2097152 float4s
        src = x; dst = (__half2*)g_Xh;
        i = bid * 256 + threadIdx.x;
    } else {                                // W[z]: 262144 float4s each
        int r = bid - 8192;
        int z = r >> 10;
        src = (z == 0) ? wq : (z == 1) ? wk : wv;
        dst = (__half2*)g_Wh[z];
        i = (r & 1023) * 256 + threadIdx.x;
    }
    float4 v = src[i];
    dst[2 * i + 0] = __floats2half2_rn(v.x, v.y);
    dst[2 * i + 1] = __floats2half2_rn(v.z, v.w);
}

// ---------------- fused QKV projection (unchanged winner) -------------------
// BK=64, CTA tile 128x128, 8 warps (warp tile 64x32), occupancy 2.
// 3-stage cp.async ring with wait_group 1.
// smem: A stages [3][128][72]h at 0 (55296 B), B stages at 55296. 110592 B.
#define QKV_SMEM 110592
__global__ __launch_bounds__(256, 2) void qkv_gemm(const float* __restrict__ bq,
                                                   const float* __restrict__ bk,
                                                   const float* __restrict__ bv) {
    extern __shared__ char qsm[];

    const int z  = blockIdx.z;
    const __half* W    = g_Wh[z];
    const float*  bias = (z == 0) ? bq : (z == 1) ? bk : bv;
    const int m0 = blockIdx.y * 128;
    const int n0 = blockIdx.x * 128;

    const int t    = threadIdx.x;
    const int warp = t >> 5, lane = t & 31;
    const int wm = warp & 1, wn = warp >> 1;

    auto load_st = [&](int st, int kb) {
#pragma unroll
        for (int i = 0; i < 4; i++) {
            int idx = t + i * 256;              // 1024 chunks of 16B per tile
            int row = idx >> 3, c = idx & 7;
            cpa16(smem_u32(qsm + st * 18432 + row * 144 + c * 16),
                  g_Xh + (size_t)(m0 + row) * 1024 + kb * 64 + c * 8);
            cpa16(smem_u32(qsm + 55296 + st * 18432 + row * 144 + c * 16),
                  W + (size_t)(n0 + row) * 1024 + kb * 64 + c * 8);
        }
    };

    float acc[4][4][4];
#pragma unroll
    for (int i = 0; i < 4; i++)
#pragma unroll
        for (int j = 0; j < 4; j++)
#pragma unroll
            for (int k = 0; k < 4; k++) acc[i][j][k] = 0.f;

    const uint32_t aOff = (uint32_t)(wm * 64 + (lane & 15)) * 144 + (lane >> 4) * 16;
    const uint32_t bOff = (uint32_t)(wn * 32 + (lane & 7) + ((lane >> 4) & 1) * 8) * 144
                        + ((lane >> 3) & 1) * 16;

    load_st(0, 0);
    CP_COMMIT();
    load_st(1, 1);
    CP_COMMIT();

    int st = 0;
    for (int kb = 0; kb < 16; kb++) {
        CP_WAIT(1);
        __syncthreads();
        if (kb + 2 < 16) load_st((kb + 2) % 3, kb + 2);
        CP_COMMIT();

        const uint32_t aAddr = smem_u32(qsm) + st * 18432 + aOff;
        const uint32_t bAddr = smem_u32(qsm) + 55296 + st * 18432 + bOff;
        st = (st == 2) ? 0 : st + 1;
#pragma unroll
        for (int kc = 0; kc < 4; kc++) {
            uint32_t a[4][4], b[2][4];
#pragma unroll
            for (int mt = 0; mt < 4; mt++) ldm4(a[mt], aAddr + kc * 32 + mt * 16 * 144);
#pragma unroll
            for (int np = 0; np < 2; np++) ldm4(b[np], bAddr + kc * 32 + np * 16 * 144);
#pragma unroll
            for (int mt = 0; mt < 4; mt++)
#pragma unroll
                for (int nt = 0; nt < 4; nt++)
                    mma16816(acc[mt][nt], a[mt], b[nt >> 1] + (nt & 1) * 2);
        }
    }

    // epilogue: bias + store into head-major scratch (fp16)
#pragma unroll
    for (int mt = 0; mt < 4; mt++) {
        int m  = m0 + wm * 64 + mt * 16 + (lane >> 2);
        int bb = m >> 11;
        int s  = m & 2047;
#pragma unroll
        for (int nt = 0; nt < 4; nt++) {
            int n  = n0 + wn * 32 + nt * 8 + (lane & 3) * 2;
            int h  = n >> 6, hd = n & 63;
            int bh = bb * 16 + h;
            float bs0 = bias[n], bs1 = bias[n + 1];
            float v00 = acc[mt][nt][0] + bs0, v01 = acc[mt][nt][1] + bs1;
            float v10 = acc[mt][nt][2] + bs0, v11 = acc[mt][nt][3] + bs1;
            if (z < 2) {
                __half* dst = (z == 0) ? g_Q : g_K;
                *(__half2*)&dst[((size_t)bh * 2048 + s    ) * 64 + hd] = __floats2half2_rn(v00, v01);
                *(__half2*)&dst[((size_t)bh * 2048 + s + 8) * 64 + hd] = __floats2half2_rn(v10, v11);
            } else {
                g_Vt[((size_t)bh * 64 + hd    ) * 2048 + s    ] = __float2half_rn(v00);
                g_Vt[((size_t)bh * 64 + hd + 1) * 2048 + s    ] = __float2half_rn(v01);
                g_Vt[((size_t)bh * 64 + hd    ) * 2048 + s + 8] = __float2half_rn(v10);
                g_Vt[((size_t)bh * 64 + hd + 1) * 2048 + s + 8] = __float2half_rn(v11);
            }
        }
    }
}

// ---------------- FlashAttention (batched-fragment inner loops) -------------
// R13 structure (128-key stages, smem mask, 4 warps x 32 q-rows) with the two
// inner loops restructured for memory-level parallelism:
//   - score: per ks, ALL 4 K-fragment ldm4 issued as a batch, then 16 HMMA
//   - PV: per kc chunk, ALL 4 V-fragment ldm4 issued BEFORE the softmax so
//     the MUFU/FMA chain hides the LDSM latency, then 16 HMMA
// Identical arithmetic and accumulation order -> identical rel_err.
// smem layout (bytes):
//   Qs [128][72] half  : 0      .. 18432
//   Ks [2][128][72]    : 18432  .. 55296   (stage = 18432)
//   Vs [2][64][136]    : 55296  .. 90112   (stage = 17408, 272B rows)
//   maskSm [2048] f32  : 90112  .. 98304
#define ATTN_SMEM 98304
__global__ __launch_bounds__(128, 2) void attn_kernel(const float* __restrict__ mask,
                                                      float* __restrict__ out) {
    extern __shared__ char sm[];
    __half (*Qs)[72] = (__half(*)[72])sm;
    char* ksBase = sm + 18432;
    char* vsBase = sm + 55296;
    float* maskSm = (float*)(sm + 90112);

    const int bh = blockIdx.y;
    const int q0 = blockIdx.x * 128;
    const int b  = bh >> 4, h = bh & 15;
    const int t = threadIdx.x, warp = t >> 5, lane = t & 31;
    const __half2 clamp14 = __floats2half2_rn(14.f, 14.f);

    // stage loader: 128-key K tile (128x72h rows) + V^T tile (64x136h rows)
    auto load_kv = [&](int st, int k0) {
#pragma unroll
        for (int i = 0; i < 8; i++) {
            int idx = t + i * 128;           // K: 1024 chunks of 16B
            int row = idx >> 3, cb = idx & 7;
            cpa16(smem_u32(ksBase + st * 18432 + row * 144 + cb * 16),
                  &g_K[((size_t)bh * 2048 + k0 + row) * 64 + cb * 8]);
        }
#pragma unroll
        for (int i = 0; i < 8; i++) {
            int idx = t + i * 128;           // V: 1024 chunks of 16B
            int row = idx >> 4, cb = idx & 15;
            cpa16(smem_u32(vsBase + st * 17408 + row * 272 + cb * 16),
                  &g_Vt[((size_t)bh * 64 + row) * 2048 + k0 + cb * 8]);
        }
    };

    load_kv(0, 0);
    CP_COMMIT();

    // one-time mask preload (scaled by LOG2E); LDGs overlap Q tile loads
#pragma unroll
    for (int i = 0; i < 16; i++)
        maskSm[t + i * 128] = mask[b * 2048 + t + i * 128] * LOG2E;

#pragma unroll
    for (int i = 0; i < 8; i++) {
        int idx = t + i * 128;              // 1024 chunks for the 128x64 Q tile
        int row = idx >> 3, c8 = (idx & 7) * 8;
        *(uint4*)&Qs[row][c8] =
            *(const uint4*)&g_Q[((size_t)bh * 2048 + q0 + row) * 64 + c8];
    }
    __syncthreads();

    // Q fragments: 2 m-tiles x 4 k-chunks
    uint32_t qa[2][4][4];
#pragma unroll
    for (int mt = 0; mt < 2; mt++) {
        uint32_t qAddr = smem_u32(&Qs[warp * 32 + mt * 16 + (lane & 15)][(lane >> 4) * 8]);
#pragma unroll
        for (int ks = 0; ks < 4; ks++) ldm4(qa[mt][ks], qAddr + ks * 32);
    }

    const uint32_t kOff = ((lane & 7) + ((lane >> 4) & 1) * 8) * 144 + ((lane >> 3) & 1) * 16;
    const uint32_t vOff = ((lane & 7) + ((lane >> 4) & 1) * 8) * 272 + ((lane >> 3) & 1) * 16;
    const uint32_t kA0 = smem_u32(ksBase) + kOff;
    const uint32_t vA0 = smem_u32(vsBase) + vOff;

    float o[2][8][4];
#pragma unroll
    for (int mt = 0; mt < 2; mt++)
#pragma unroll
        for (int i = 0; i < 8; i++)
#pragma unroll
            for (int j = 0; j < 4; j++) o[mt][i][j] = 0.f;
    float l00 = 0.f, l01 = 0.f, l10 = 0.f, l11 = 0.f;

    for (int kt = 0; kt < 16; kt++) {
        CP_WAIT(0);                    // stage kt resident
        __syncthreads();               // stage kt-1 fully consumed by all warps
        if (kt + 1 < 16) load_kv((kt + 1) & 1, (kt + 1) * 128);
        CP_COMMIT();

        const int stg = kt & 1;
#pragma unroll
        for (int hh = 0; hh < 2; hh++) {
            const uint32_t kA = kA0 + stg * 18432 + hh * 64 * 144;
            const uint32_t vA = vA0 + stg * 17408 + hh * 128;   // 64 keys * 2B
            const float* mk = maskSm + kt * 128 + hh * 64;

            // scores: 32 q-rows x 64 keys; K fragments batched per ks (MLP=4)
            float sc[2][8][4];
#pragma unroll
            for (int mt = 0; mt < 2; mt++)
#pragma unroll
                for (int nt = 0; nt < 8; nt++)
#pragma unroll
                    for (int j = 0; j < 4; j++) sc[mt][nt][j] = 0.f;
#pragma unroll
            for (int ks = 0; ks < 4; ks++) {
                uint32_t kf[4][4];
#pragma unroll
                for (int np = 0; np < 4; np++)
                    ldm4(kf[np], kA + np * 16 * 144 + ks * 32);
#pragma unroll
                for (int np = 0; np < 4; np++)
#pragma unroll
                    for (int mt = 0; mt < 2; mt++) {
                        mma16816(sc[mt][2*np    ], qa[mt][ks], kf[np]);
                        mma16816(sc[mt][2*np + 1], qa[mt][ks], kf[np] + 2);
                    }
            }

            // chunk-interleaved softmax + PV; V fragments batched BEFORE the
            // softmax so the MUFU chain hides their latency
#pragma unroll
            for (int kc = 0; kc < 4; kc++) {
                uint32_t vf[4][4];
#pragma unroll
                for (int hp = 0; hp < 4; hp++)
                    ldm4(vf[hp], vA + hp * 16 * 272 + kc * 32);

                uint32_t ph[2][4];
#pragma unroll
                for (int mt = 0; mt < 2; mt++) {
                    float lp0 = 0.f, lp1 = 0.f;
#pragma unroll
                    for (int u = 0; u < 2; u++) {
                        int nt = 2 * kc + u;
                        int key = nt * 8 + (lane & 3) * 2;
                        float mk0v = mk[key], mk1v = mk[key + 1];
                        float s0 = fmaf(sc[mt][nt][0], SCL, mk0v);
                        float s1 = fmaf(sc[mt][nt][1], SCL, mk1v);
                        float s2 = fmaf(sc[mt][nt][2], SCL, mk0v);
                        float s3 = fmaf(sc[mt][nt][3], SCL, mk1v);
                        ph[mt][2*u    ] = h2ex2(s0, s1, clamp14);
                        ph[mt][2*u + 1] = h2ex2(s2, s3, clamp14);
                        float2 f0 = __half22float2(*reinterpret_cast<__half2*>(&ph[mt][2*u]));
                        float2 f1 = __half22float2(*reinterpret_cast<__half2*>(&ph[mt][2*u+1]));
                        lp0 += f0.x + f0.y;
                        lp1 += f1.x + f1.y;
                    }
                    if (mt == 0) { l00 += lp0; l01 += lp1; }
                    else         { l10 += lp0; l11 += lp1; }
                }
#pragma unroll
                for (int hp = 0; hp < 4; hp++)
#pragma unroll
                    for (int mt = 0; mt < 2; mt++) {
                        mma16816(o[mt][2*hp    ], ph[mt], vf[hp]);
                        mma16816(o[mt][2*hp + 1], ph[mt], vf[hp] + 2);
                    }
            }
        }
    }

    // epilogue: one cross-lane reduction, normalize, store fp32 [B,S,D]
    l00 += __shfl_xor_sync(0xffffffffu, l00, 1);
    l00 += __shfl_xor_sync(0xffffffffu, l00, 2);
    l01 += __shfl_xor_sync(0xffffffffu, l01, 1);
    l01 += __shfl_xor_sync(0xffffffffu, l01, 2);
    l10 += __shfl_xor_sync(0xffffffffu, l10, 1);
    l10 += __shfl_xor_sync(0xffffffffu, l10, 2);
    l11 += __shfl_xor_sync(0xffffffffu, l11, 1);
    l11 += __shfl_xor_sync(0xffffffffu, l11, 2);
    const int cb = h * 64 + (lane & 3) * 2;
#pragma unroll
    for (int mt = 0; mt < 2; mt++) {
        float rl0 = 1.f / (mt ? l10 : l00);
        float rl1 = 1.f / (mt ? l11 : l01);
        int s0 = q0 + warp * 32 + mt * 16 + (lane >> 2);
#pragma unroll
        for (int ht = 0; ht < 8; ht++) {
            int c = cb + ht * 8;
            float2 v0 = make_float2(o[mt][ht][0] * rl0, o[mt][ht][1] * rl0);
            float2 v1 = make_float2(o[mt][ht][2] * rl1, o[mt][ht][3] * rl1);
            *(float2*)&out[((size_t)b * 2048 + s0    ) * 1024 + c] = v0;
            *(float2*)&out[((size_t)b * 2048 + s0 + 8) * 1024 + c] = v1;
        }
    }
}

// ---------------- launch -----------------------------------------------------
extern "C" void kernel_launch(void* const* d_in, const int* in_sizes, int n_in,
                              void* d_out, int out_size) {
    const float* hidden = (const float*)d_in[0];
    const float* mask   = (const float*)d_in[1];
    const float* Wq     = (const float*)d_in[2];
    const float* bq     = (const float*)d_in[3];
    const float* Wk     = (const float*)d_in[4];
    const float* bk     = (const float*)d_in[5];
    const float* Wv     = (const float*)d_in[6];
    const float* bv     = (const float*)d_in[7];
    float* out = (float*)d_out;

    cudaFuncSetAttribute(qkv_gemm, cudaFuncAttributeMaxDynamicSharedMemorySize, QKV_SMEM);
    cudaFuncSetAttribute(attn_kernel, cudaFuncAttributeMaxDynamicSharedMemorySize, ATTN_SMEM);

    cvt_all<<<11264, 256>>>((const float4*)hidden, (const float4*)Wq,
                            (const float4*)Wk, (const float4*)Wv);

    dim3 g1(8, 64, 3);      // N-blocks, M-blocks, {Q,K,V}
    qkv_gemm<<<g1, 256, QKV_SMEM>>>(bq, bk, bv);

    dim3 g2(16, 64);        // q-tiles (128 rows), B*H
    attn_kernel<<<g2, 128, ATTN_SMEM>>>(mask, out);
}